// round 4
// baseline (speedup 1.0000x reference)
#include <cuda_runtime.h>
#include <math.h>

#define NB 8
#define NA 21504
#define NG 60
#define NC 15
#define BA (NB*NA)
#define NBG (NB*NG)
#define L0N 16384
#define L1N 20480
#define LOG4F 1.3862943611198906f

// ---------------- static device scratch ----------------
__device__ float g_bx[BA], g_by[BA];
__device__ float g_a2[BA], g_b2[BA], g_c2[BA], g_d2s[BA], g_ld2[BA];
__device__ float g_obj[BA], g_S[BA];
__device__ float g_lc[NC*BA];                 // [c][b*A+a]
__device__ float2 g_ic[(size_t)NBG*NA];       // {iou, cost} per [(b*G+g)][a]
__device__ float g_gcx[NBG], g_gcy[NBG], g_ghw[NBG], g_ghh[NBG];
__device__ float g_ga1[NBG], g_gb1[NBG], g_gc1[NBG], g_gd1s[NBG], g_gld1[NBG];
__device__ int   g_gcls[NBG], g_gvalid[NBG];
__device__ int   g_dynk[NBG];
__device__ float g_thrC[NBG];
__device__ int   g_thrI[NBG];
__device__ float g_acc[5];   // 0: sum(1-iou_m), 1: bce_obj, 2: bce_cls, 3: num_fg, 4: num_gts

// ---------------- K1b: GT prep + zero accumulators (1 block) ----------------
__global__ void k_gt(const float* __restrict__ labels) {
    int t = threadIdx.x;
    if (t < 5) g_acc[t] = 0.f;
    __syncthreads();
    if (t >= NBG) return;
    const float* L = labels + (size_t)t * 6;
    float l0 = L[0], l1 = L[1], l2 = L[2], l3 = L[3], l4 = L[4], l5 = L[5];
    float sum = l0 + l1 + l2 + l3 + l4 + l5;
    int valid = (sum > 0.f) ? 1 : 0;
    float sn, cs; __sincosf(l5, &sn, &cs);
    float w2 = l3*l3/12.0f, h2 = l4*l4/12.0f;
    float a1 = w2*cs*cs + h2*sn*sn;
    float b1 = w2*sn*sn + h2*cs*cs;
    float c1 = (w2 - h2) * cs * sn;
    float d1 = fmaxf(a1*b1 - c1*c1, 0.f);
    float d1s = d1 * __frsqrt_rn(fmaxf(d1, 1e-30f));
    g_gcx[t] = l1; g_gcy[t] = l2;
    g_ghw[t] = 0.5f * l3; g_ghh[t] = 0.5f * l4;
    g_ga1[t] = a1; g_gb1[t] = b1; g_gc1[t] = c1;
    g_gd1s[t] = d1s;
    g_gld1[t] = __logf(fmaxf(d1s, 1e-35f));
    g_gcls[t] = (int)l0;
    g_gvalid[t] = valid;
    if (valid) atomicAdd(&g_acc[4], 1.f);
}

// ---------------- K1: decode anchors ----------------
__global__ void k_decode(const float* __restrict__ o8,
                         const float* __restrict__ o16,
                         const float* __restrict__ o32) {
    int t = blockIdx.x * blockDim.x + threadIdx.x;
    if (t >= BA) return;
    int b = t / NA;
    int a = t - b * NA;
    const float* src; int hw, i; float st; int gx, gy;
    if (a < L0N)       { src = o8;  hw = 16384; i = a;        st = 8.f;  gx = i & 127; gy = i >> 7; }
    else if (a < L1N)  { src = o16; hw = 4096;  i = a - L0N;  st = 16.f; gx = i & 63;  gy = i >> 6; }
    else               { src = o32; hw = 1024;  i = a - L1N;  st = 32.f; gx = i & 31;  gy = i >> 5; }
    const float* p0 = src + (size_t)b * 21 * hw + i;
    float r0 = p0[0], r1 = p0[hw], r2 = p0[2*hw], r3 = p0[3*hw], r4 = p0[4*hw], r5 = p0[5*hw];
    float bx = (r0 + (float)gx) * st;
    float by = (r1 + (float)gy) * st;
    float bw = __expf(r2) * st;
    float bh = __expf(r3) * st;
    float sn, cs; __sincosf(r4, &sn, &cs);
    float w2 = bw * bw / 12.0f, h2 = bh * bh / 12.0f;
    float a2 = w2*cs*cs + h2*sn*sn;
    float b2 = w2*sn*sn + h2*cs*cs;
    float c2 = (w2 - h2) * cs * sn;
    float d2 = fmaxf(a2*b2 - c2*c2, 0.f);
    float d2s = d2 * __frsqrt_rn(fmaxf(d2, 1e-30f));
    g_bx[t] = bx; g_by[t] = by;
    g_a2[t] = a2; g_b2[t] = b2; g_c2[t] = c2;
    g_d2s[t] = d2s;
    g_ld2[t] = __logf(fmaxf(d2s, 1e-35f));
    g_obj[t] = r5;
    float so = __fdividef(1.f, 1.f + __expf(-r5));
    float S = 0.f;
    #pragma unroll
    for (int c = 0; c < NC; c++) {
        float x = p0[(6 + c) * hw];
        float sc = __fdividef(1.f, 1.f + __expf(-x));
        float q = sc * so;
        float p = q * __frsqrt_rn(fmaxf(q, 1e-30f));
        p = fminf(fmaxf(p, 1e-7f), 1.f - 1e-7f);
        float lg = __logf(1.f - p);
        float lp = __logf(p);
        S -= lg;
        g_lc[c * BA + t] = lg - lp;
    }
    g_S[t] = S;
}

// ---------------- K2: dense ious + cost (2 anchors / thread) ----------------
__global__ void k_cost() {
    int b = blockIdx.x / 84;                // NA/256 = 84 tiles per batch
    int tile = blockIdx.x - b * 84;
    int tid = threadIdx.x;
    int a0 = tile * 256 + tid;              // anchors a0 and a0+128 (same level)
    int t0 = b * NA + a0;
    __shared__ float s_cx[NG], s_cy[NG], s_hw[NG], s_hh[NG];
    __shared__ float s_a1[NG], s_b1[NG], s_c1[NG], s_ld1[NG];
    __shared__ int   s_cls[NG], s_val[NG];
    if (tid < NG) {
        int gi = b * NG + tid;
        int v = g_gvalid[gi];
        s_val[tid] = v;
        s_cx[tid] = v ? g_gcx[gi] : 3.0e9f;   // invalid -> centers far away: no ib/ic
        s_cy[tid] = v ? g_gcy[gi] : 3.0e9f;
        s_hw[tid] = g_ghw[gi]; s_hh[tid] = g_ghh[gi];
        s_a1[tid] = g_ga1[gi]; s_b1[tid] = g_gb1[gi];
        s_c1[tid] = g_gc1[gi]; s_ld1[tid] = g_gld1[gi];
        s_cls[tid] = g_gcls[gi];
    }
    __syncthreads();
    float st; int lvlbase, shx, mskx;
    if (a0 < L0N)      { st = 8.f;  lvlbase = 0;    shx = 7; mskx = 127; }
    else if (a0 < L1N) { st = 16.f; lvlbase = L0N;  shx = 6; mskx = 63; }
    else               { st = 32.f; lvlbase = L1N;  shx = 5; mskx = 31; }
    int i0 = a0 - lvlbase, i1 = i0 + 128;
    float xc0 = ((float)(i0 & mskx) + 0.5f) * st;
    float yc0 = ((float)(i0 >> shx) + 0.5f) * st;
    float xc1 = ((float)(i1 & mskx) + 0.5f) * st;
    float yc1 = ((float)(i1 >> shx) + 0.5f) * st;
    float rad = 2.5f * st;

    float bx0 = g_bx[t0],   by0 = g_by[t0];
    float bx1 = g_bx[t0+128], by1 = g_by[t0+128];
    float A0 = g_a2[t0], B0 = g_b2[t0], C0 = g_c2[t0];
    float A1 = g_a2[t0+128], B1 = g_b2[t0+128], C1 = g_c2[t0+128];
    float S0 = g_S[t0], S1 = g_S[t0+128];
    float lb0 = g_ld2[t0] + LOG4F, lb1 = g_ld2[t0+128] + LOG4F;

    unsigned long long both0 = 0ULL, both1 = 0ULL;
    bool c0 = false, c1 = false;
    #pragma unroll 4
    for (int g = 0; g < NG; g++) {
        float cx = s_cx[g], cy = s_cy[g], hw = s_hw[g], hh = s_hh[g];
        float dx0 = fabsf(xc0 - cx), dy0 = fabsf(yc0 - cy);
        float dx1 = fabsf(xc1 - cx), dy1 = fabsf(yc1 - cy);
        bool ib0 = (dx0 < hw) & (dy0 < hh);
        bool ic0 = (dx0 < rad) & (dy0 < rad);
        bool ib1 = (dx1 < hw) & (dy1 < hh);
        bool ic1 = (dx1 < rad) & (dy1 < rad);
        c0 |= ib0 | ic0; c1 |= ib1 | ic1;
        if (ib0 & ic0) both0 |= (1ULL << g);
        if (ib1 & ic1) both1 |= (1ULL << g);
    }
    float pc0 = c0 ? 0.f : 1e6f;
    float pc1 = c1 ? 0.f : 1e6f;
    size_t rowbase = (size_t)b * NG * NA + a0;

    for (int g = 0; g < NG; g++) {
        float2* dst = g_ic + rowbase + (size_t)g * NA;
        if (!s_val[g]) {
            dst[0]   = make_float2(0.f, 2e9f);
            dst[128] = make_float2(0.f, 2e9f);
            continue;
        }
        float ga = s_a1[g], gb = s_b1[g], gc = s_c1[g];
        float cx = s_cx[g], cy = s_cy[g];
        float lg1 = s_ld1[g];
        float lc0 = g_lc[s_cls[g] * BA + t0];
        float lc1 = g_lc[s_cls[g] * BA + t0 + 128];
        // anchor 0
        {
            float Af = ga + A0, Bf = gb + B0, Cf = gc + C0;
            float dx = cx - bx0, dy = cy - by0;
            float den = Af * Bf - Cf * Cf + 1e-8f;
            float rden = __fdividef(1.f, den);
            float t1 = 0.25f * (Af*dy*dy + Bf*dx*dx) * rden;
            float t2 = -0.5f * Cf * dx * dy * rden;
            float t3 = 0.5f * (__logf(den) - (lg1 + lb0));
            float bd = fminf(fmaxf(t1 + t2 + t3, 1e-8f), 100.f);
            float q = fminf(fmaxf(1.f - __expf(-bd), 1e-20f), 1.f);
            float iou = 1.f - q * __frsqrt_rn(q);
            float pb = ((both0 >> g) & 1ULL) ? 0.f : 1e5f;
            float cost = fmaf(-3.f, __logf(iou + 1e-8f), S0 + lc0 + pb + pc0);
            dst[0] = make_float2(iou, cost);
        }
        // anchor 1
        {
            float Af = ga + A1, Bf = gb + B1, Cf = gc + C1;
            float dx = cx - bx1, dy = cy - by1;
            float den = Af * Bf - Cf * Cf + 1e-8f;
            float rden = __fdividef(1.f, den);
            float t1 = 0.25f * (Af*dy*dy + Bf*dx*dx) * rden;
            float t2 = -0.5f * Cf * dx * dy * rden;
            float t3 = 0.5f * (__logf(den) - (lg1 + lb1));
            float bd = fminf(fmaxf(t1 + t2 + t3, 1e-8f), 100.f);
            float q = fminf(fmaxf(1.f - __expf(-bd), 1e-20f), 1.f);
            float iou = 1.f - q * __frsqrt_rn(q);
            float pb = ((both1 >> g) & 1ULL) ? 0.f : 1e5f;
            float cost = fmaf(-3.f, __logf(iou + 1e-8f), S1 + lc1 + pb + pc1);
            dst[128] = make_float2(iou, cost);
        }
    }
}

// ---------------- K3: per-(b,g) dyn_k + matching threshold ----------------
__device__ __forceinline__ bool pless(float c1, int i1, float c2, int i2) {
    return (c1 < c2) || (c1 == c2 && i1 < i2);
}

// max-10 of values: top[0] = smallest kept (eviction point), top[9] = largest
__device__ __forceinline__ void ins_top(float (&top)[10], float v) {
    if (v > top[0]) {
        top[0] = v;
        #pragma unroll
        for (int i = 0; i < 9; i++) {
            float lo = fminf(top[i], top[i+1]);
            float hi = fmaxf(top[i], top[i+1]);
            top[i] = lo; top[i+1] = hi;
        }
    }
}
// min-10 pairs: bc[0] = largest kept (eviction point), bc[9] = smallest
__device__ __forceinline__ void ins_bot(float (&bc)[10], int (&bi)[10], float c, int ii) {
    if (pless(c, ii, bc[0], bi[0])) {
        bc[0] = c; bi[0] = ii;
        #pragma unroll
        for (int i = 0; i < 9; i++) {
            if (pless(bc[i], bi[i], bc[i+1], bi[i+1])) {
                float tc = bc[i]; bc[i] = bc[i+1]; bc[i+1] = tc;
                int ti = bi[i]; bi[i] = bi[i+1]; bi[i+1] = ti;
            }
        }
    }
}
// snapshot-then-insert pair merge (both lanes read partner's pristine state first)
__device__ __forceinline__ void merge_xor(float (&top)[10], float (&bc)[10], int (&bi)[10], int off) {
    float tv[10], cv[10]; int iv[10];
    #pragma unroll
    for (int j = 0; j < 10; j++) {
        tv[j] = __shfl_xor_sync(0xffffffffu, top[j], off);
        cv[j] = __shfl_xor_sync(0xffffffffu, bc[j], off);
        iv[j] = __shfl_xor_sync(0xffffffffu, bi[j], off);
    }
    #pragma unroll
    for (int j = 0; j < 10; j++) {
        ins_top(top, tv[j]);
        ins_bot(bc, bi, cv[j], iv[j]);
    }
}

__global__ void k_select() {
    int bg = blockIdx.x;
    int tid = threadIdx.x;
    if (!g_gvalid[bg]) {
        if (tid == 0) { g_dynk[bg] = 0; g_thrC[bg] = -3.0e38f; g_thrI[bg] = -1; }
        return;
    }
    const float4* __restrict__ row4 = (const float4*)(g_ic + (size_t)bg * NA);

    float top[10]; float bc[10]; int bi[10];
    #pragma unroll
    for (int i = 0; i < 10; i++) { top[i] = -1.f; bc[i] = 3.0e38f; bi[i] = 0x7fffffff; }

    for (int i = tid; i < NA/2; i += 256) {
        float4 v = row4[i];                 // anchors 2i (x=iou,y=cost), 2i+1 (z,w)
        int a0 = 2*i, a1 = 2*i + 1;
        float e0 = (v.y < 1e6f) ? v.x : 0.f;   // cand <=> cost < 1e6 (penalty separation)
        float e1 = (v.w < 1e6f) ? v.z : 0.f;
        ins_top(top, e0);
        ins_top(top, e1);
        ins_bot(bc, bi, v.y, a0);
        ins_bot(bc, bi, v.w, a1);
    }

    // intra-warp butterfly merge (snapshot semantics -> exact union at each stage)
    merge_xor(top, bc, bi, 16);
    merge_xor(top, bc, bi, 8);
    merge_xor(top, bc, bi, 4);
    merge_xor(top, bc, bi, 2);
    merge_xor(top, bc, bi, 1);

    __shared__ float s_top[8][10], s_bc[8][10];
    __shared__ int   s_bi[8][10];
    int w = tid >> 5, lane = tid & 31;
    if (lane == 0) {
        #pragma unroll
        for (int j = 0; j < 10; j++) { s_top[w][j] = top[j]; s_bc[w][j] = bc[j]; s_bi[w][j] = bi[j]; }
    }
    __syncthreads();

    if (w == 0) {
        if (lane < 8) {
            #pragma unroll
            for (int j = 0; j < 10; j++) { top[j] = s_top[lane][j]; bc[j] = s_bc[lane][j]; bi[j] = s_bi[lane][j]; }
        } else {
            #pragma unroll
            for (int j = 0; j < 10; j++) { top[j] = -1.f; bc[j] = 3.0e38f; bi[j] = 0x7fffffff; }
        }
        merge_xor(top, bc, bi, 4);
        merge_xor(top, bc, bi, 2);
        merge_xor(top, bc, bi, 1);
        if (lane == 0) {
            float sum = 0.f;
            #pragma unroll
            for (int j = 0; j < 10; j++) sum += top[j];
            int k = (int)sum;
            if (k < 1) k = 1;
            if (k > 10) k = 10;
            g_dynk[bg] = k;
            // dynamic index via shared, keeps bc/bi in registers
            #pragma unroll
            for (int j = 0; j < 10; j++) { s_bc[0][j] = bc[j]; s_bi[0][j] = bi[j]; }
            g_thrC[bg] = s_bc[0][10 - k];
            g_thrI[bg] = s_bi[0][10 - k];
        }
    }
}

// ---------------- K5: match resolution + loss accumulation ----------------
__global__ void k_loss(const float* __restrict__ o8,
                       const float* __restrict__ o16,
                       const float* __restrict__ o32) {
    int b = blockIdx.x / 168;
    int t = blockIdx.x * 128 + threadIdx.x;
    int a = t - b * NA;
    __shared__ float s_thrC[NG], s_cx[NG], s_cy[NG], s_a1[NG], s_b1[NG], s_c1[NG], s_d1s[NG];
    __shared__ int   s_thrI[NG], s_k[NG], s_cls[NG];
    if (threadIdx.x < NG) {
        int gi = b * NG + threadIdx.x;
        s_thrC[threadIdx.x] = g_thrC[gi]; s_thrI[threadIdx.x] = g_thrI[gi]; s_k[threadIdx.x] = g_dynk[gi];
        s_cx[threadIdx.x] = g_gcx[gi]; s_cy[threadIdx.x] = g_gcy[gi];
        s_a1[threadIdx.x] = g_ga1[gi]; s_b1[threadIdx.x] = g_gb1[gi]; s_c1[threadIdx.x] = g_gc1[gi];
        s_d1s[threadIdx.x] = g_gd1s[gi]; s_cls[threadIdx.x] = g_gcls[gi];
    }
    __syncthreads();
    const float2* __restrict__ col = g_ic + (size_t)b * NG * NA + a;
    int cnt = 0, mg = 0, ming = 0;
    bool found = false;
    float minc = 3.4e38f, miniou = 0.f, pisum = 0.f;
    #pragma unroll 4
    for (int g = 0; g < NG; g++) {
        float2 ic = col[(size_t)g * NA];
        bool m = (s_k[g] > 0) && ((ic.y < s_thrC[g]) || (ic.y == s_thrC[g] && a <= s_thrI[g]));
        if (m) { cnt++; if (!found) { mg = g; found = true; } pisum += ic.x; }
        if (ic.y < minc) { minc = ic.y; ming = g; miniou = ic.x; }
    }
    bool fg = cnt > 0;
    float pi = pisum;
    if (cnt > 1) { mg = ming; pi = miniou; }   // conflict -> one-hot argmin
    float obj = g_obj[t];
    float fo = fg ? 1.f : 0.f;
    float lobj = fmaxf(obj, 0.f) - obj * fo + __logf(1.f + __expf(-fabsf(obj)));
    float liou = 0.f, lcls = 0.f;
    if (fg) {
        float bx = g_bx[t], by = g_by[t];
        float a2 = g_a2[t], b2 = g_b2[t], c2 = g_c2[t], d2s = g_d2s[t];
        float Af = a2 + s_a1[mg], Bf = b2 + s_b1[mg], Cf = c2 + s_c1[mg];
        float dx = bx - s_cx[mg], dy = by - s_cy[mg];
        float den = Af * Bf - Cf * Cf + 1e-8f;
        float rden = __fdividef(1.f, den);
        float t1 = 0.25f * (Af*dy*dy + Bf*dx*dx) * rden;
        float t2 = -0.5f * Cf * dx * dy * rden;
        float t3 = 0.5f * __logf(__fdividef(den, 4.f * s_d1s[mg] * d2s + 1e-8f));
        float bd = fminf(fmaxf(t1 + t2 + t3, 1e-8f), 100.f);
        float q = fminf(fmaxf(1.f - __expf(-bd), 1e-20f), 1.f);
        float ioum = 1.f - q * __frsqrt_rn(q);
        liou = 1.f - ioum;
        const float* src; int hw, i;
        if (a < L0N)      { src = o8;  hw = 16384; i = a; }
        else if (a < L1N) { src = o16; hw = 4096;  i = a - L0N; }
        else              { src = o32; hw = 1024;  i = a - L1N; }
        const float* pc = src + ((size_t)b * 21 + 6) * hw + i;
        int mcls = s_cls[mg];
        #pragma unroll
        for (int c = 0; c < NC; c++) {
            float x = pc[(size_t)c * hw];
            float tg = (c == mcls) ? pi : 0.f;
            lcls += fmaxf(x, 0.f) - x * tg + __logf(1.f + __expf(-fabsf(x)));
        }
    }
    #pragma unroll
    for (int o = 16; o > 0; o >>= 1) {
        liou += __shfl_down_sync(0xffffffffu, liou, o);
        lobj += __shfl_down_sync(0xffffffffu, lobj, o);
        lcls += __shfl_down_sync(0xffffffffu, lcls, o);
        fo   += __shfl_down_sync(0xffffffffu, fo, o);
    }
    __shared__ float rs[4][4];
    int w = threadIdx.x >> 5, lane = threadIdx.x & 31;
    if (lane == 0) { rs[0][w] = liou; rs[1][w] = lobj; rs[2][w] = lcls; rs[3][w] = fo; }
    __syncthreads();
    if (threadIdx.x == 0) {
        atomicAdd(&g_acc[0], rs[0][0] + rs[0][1] + rs[0][2] + rs[0][3]);
        atomicAdd(&g_acc[1], rs[1][0] + rs[1][1] + rs[1][2] + rs[1][3]);
        atomicAdd(&g_acc[2], rs[2][0] + rs[2][1] + rs[2][2] + rs[2][3]);
        atomicAdd(&g_acc[3], rs[3][0] + rs[3][1] + rs[3][2] + rs[3][3]);
    }
}

// ---------------- K6: finalize ----------------
__global__ void k_final(float* __restrict__ out, int n) {
    if (threadIdx.x == 0) {
        float nfg = g_acc[3];
        float nf = fmaxf(nfg, 1.f);
        float liou = g_acc[0] / nf;
        float lobj = g_acc[1] / nf;
        float lcls = g_acc[2] / nf;
        float li5 = 5.f * liou;
        float loss = li5 + lobj + lcls;
        if (n > 0) out[0] = loss;
        if (n > 1) out[1] = li5;
        if (n > 2) out[2] = lobj;
        if (n > 3) out[3] = lcls;
        if (n > 4) out[4] = 0.f;
        if (n > 5) out[5] = nfg / fmaxf(g_acc[4], 1.f);
        for (int i = 6; i < n; i++) out[i] = 0.f;
    }
}

// ---------------- launch ----------------
extern "C" void kernel_launch(void* const* d_in, const int* in_sizes, int n_in,
                              void* d_out, int out_size) {
    const float* o8     = (const float*)d_in[0];
    const float* o16    = (const float*)d_in[1];
    const float* o32    = (const float*)d_in[2];
    const float* labels = (const float*)d_in[3];
    float* out = (float*)d_out;

    k_gt<<<1, 512>>>(labels);
    k_decode<<<BA / 128, 128>>>(o8, o16, o32);
    k_cost<<<672, 128>>>();
    k_select<<<NBG, 256>>>();
    k_loss<<<BA / 128, 128>>>(o8, o16, o32);
    k_final<<<1, 32>>>(out, out_size);
}

// round 5
// speedup vs baseline: 2.4748x; 2.4748x over previous
#include <cuda_runtime.h>
#include <math.h>

#define NB 8
#define NA 21504
#define NG 60
#define NC 15
#define BA (NB*NA)
#define NBG (NB*NG)
#define L0N 16384
#define L1N 20480
#define LOG4F 1.3862943611198906f
#define FULLM 0xffffffffu

// ---------------- static device scratch ----------------
__device__ float g_bx[BA], g_by[BA];
__device__ float g_a2[BA], g_b2[BA], g_c2[BA], g_d2s[BA], g_ld2[BA];
__device__ float g_obj[BA], g_S[BA];
__device__ float g_lc[NC*BA];                 // [c][b*A+a]
__device__ float2 g_ic[(size_t)NBG*NA];       // {iou, cost} per [(b*G+g)][a]
__device__ float g_gcx[NBG], g_gcy[NBG], g_ghw[NBG], g_ghh[NBG];
__device__ float g_ga1[NBG], g_gb1[NBG], g_gc1[NBG], g_gd1s[NBG], g_gld1[NBG];
__device__ int   g_gcls[NBG], g_gvalid[NBG];
__device__ int   g_dynk[NBG];
__device__ float g_thrC[NBG];
__device__ int   g_thrI[NBG];
__device__ float g_acc[5];   // 0: sum(1-iou_m), 1: bce_obj, 2: bce_cls, 3: num_fg, 4: num_gts

// ---------------- K1b: GT prep + zero accumulators (1 block) ----------------
__global__ void k_gt(const float* __restrict__ labels) {
    int t = threadIdx.x;
    if (t < 5) g_acc[t] = 0.f;
    __syncthreads();
    if (t >= NBG) return;
    const float* L = labels + (size_t)t * 6;
    float l0 = L[0], l1 = L[1], l2 = L[2], l3 = L[3], l4 = L[4], l5 = L[5];
    float sum = l0 + l1 + l2 + l3 + l4 + l5;
    int valid = (sum > 0.f) ? 1 : 0;
    float sn, cs; __sincosf(l5, &sn, &cs);
    float w2 = l3*l3/12.0f, h2 = l4*l4/12.0f;
    float a1 = w2*cs*cs + h2*sn*sn;
    float b1 = w2*sn*sn + h2*cs*cs;
    float c1 = (w2 - h2) * cs * sn;
    float d1 = fmaxf(a1*b1 - c1*c1, 0.f);
    float d1s = d1 * __frsqrt_rn(fmaxf(d1, 1e-30f));
    g_gcx[t] = l1; g_gcy[t] = l2;
    g_ghw[t] = 0.5f * l3; g_ghh[t] = 0.5f * l4;
    g_ga1[t] = a1; g_gb1[t] = b1; g_gc1[t] = c1;
    g_gd1s[t] = d1s;
    g_gld1[t] = __logf(fmaxf(d1s, 1e-35f));
    g_gcls[t] = (int)l0;
    g_gvalid[t] = valid;
    if (valid) atomicAdd(&g_acc[4], 1.f);
}

// ---------------- K1: decode anchors ----------------
__global__ void k_decode(const float* __restrict__ o8,
                         const float* __restrict__ o16,
                         const float* __restrict__ o32) {
    int t = blockIdx.x * blockDim.x + threadIdx.x;
    if (t >= BA) return;
    int b = t / NA;
    int a = t - b * NA;
    const float* src; int hw, i; float st; int gx, gy;
    if (a < L0N)       { src = o8;  hw = 16384; i = a;        st = 8.f;  gx = i & 127; gy = i >> 7; }
    else if (a < L1N)  { src = o16; hw = 4096;  i = a - L0N;  st = 16.f; gx = i & 63;  gy = i >> 6; }
    else               { src = o32; hw = 1024;  i = a - L1N;  st = 32.f; gx = i & 31;  gy = i >> 5; }
    const float* p0 = src + (size_t)b * 21 * hw + i;
    float r0 = p0[0], r1 = p0[hw], r2 = p0[2*hw], r3 = p0[3*hw], r4 = p0[4*hw], r5 = p0[5*hw];
    float bx = (r0 + (float)gx) * st;
    float by = (r1 + (float)gy) * st;
    float bw = __expf(r2) * st;
    float bh = __expf(r3) * st;
    float sn, cs; __sincosf(r4, &sn, &cs);
    float w2 = bw * bw / 12.0f, h2 = bh * bh / 12.0f;
    float a2 = w2*cs*cs + h2*sn*sn;
    float b2 = w2*sn*sn + h2*cs*cs;
    float c2 = (w2 - h2) * cs * sn;
    float d2 = fmaxf(a2*b2 - c2*c2, 0.f);
    float d2s = d2 * __frsqrt_rn(fmaxf(d2, 1e-30f));
    g_bx[t] = bx; g_by[t] = by;
    g_a2[t] = a2; g_b2[t] = b2; g_c2[t] = c2;
    g_d2s[t] = d2s;
    g_ld2[t] = __logf(fmaxf(d2s, 1e-35f));
    g_obj[t] = r5;
    float so = __fdividef(1.f, 1.f + __expf(-r5));
    float S = 0.f;
    #pragma unroll
    for (int c = 0; c < NC; c++) {
        float x = p0[(6 + c) * hw];
        float sc = __fdividef(1.f, 1.f + __expf(-x));
        float q = sc * so;
        float p = q * __frsqrt_rn(fmaxf(q, 1e-30f));
        p = fminf(fmaxf(p, 1e-7f), 1.f - 1e-7f);
        float lg = __logf(1.f - p);
        float lp = __logf(p);
        S -= lg;
        g_lc[c * BA + t] = lg - lp;
    }
    g_S[t] = S;
}

// ---------------- K2: dense ious + cost (2 anchors / thread) ----------------
__global__ void k_cost() {
    int b = blockIdx.x / 84;                // NA/256 = 84 tiles per batch
    int tile = blockIdx.x - b * 84;
    int tid = threadIdx.x;
    int a0 = tile * 256 + tid;              // anchors a0 and a0+128 (same level)
    int t0 = b * NA + a0;
    __shared__ float s_cx[NG], s_cy[NG], s_hw[NG], s_hh[NG];
    __shared__ float s_a1[NG], s_b1[NG], s_c1[NG], s_ld1[NG];
    __shared__ int   s_cls[NG], s_val[NG];
    if (tid < NG) {
        int gi = b * NG + tid;
        int v = g_gvalid[gi];
        s_val[tid] = v;
        s_cx[tid] = v ? g_gcx[gi] : 3.0e9f;   // invalid -> centers far away: no ib/ic
        s_cy[tid] = v ? g_gcy[gi] : 3.0e9f;
        s_hw[tid] = g_ghw[gi]; s_hh[tid] = g_ghh[gi];
        s_a1[tid] = g_ga1[gi]; s_b1[tid] = g_gb1[gi];
        s_c1[tid] = g_gc1[gi]; s_ld1[tid] = g_gld1[gi];
        s_cls[tid] = g_gcls[gi];
    }
    __syncthreads();
    float st; int lvlbase, shx, mskx;
    if (a0 < L0N)      { st = 8.f;  lvlbase = 0;    shx = 7; mskx = 127; }
    else if (a0 < L1N) { st = 16.f; lvlbase = L0N;  shx = 6; mskx = 63; }
    else               { st = 32.f; lvlbase = L1N;  shx = 5; mskx = 31; }
    int i0 = a0 - lvlbase, i1 = i0 + 128;
    float xc0 = ((float)(i0 & mskx) + 0.5f) * st;
    float yc0 = ((float)(i0 >> shx) + 0.5f) * st;
    float xc1 = ((float)(i1 & mskx) + 0.5f) * st;
    float yc1 = ((float)(i1 >> shx) + 0.5f) * st;
    float rad = 2.5f * st;

    float bx0 = g_bx[t0],   by0 = g_by[t0];
    float bx1 = g_bx[t0+128], by1 = g_by[t0+128];
    float A0 = g_a2[t0], B0 = g_b2[t0], C0 = g_c2[t0];
    float A1 = g_a2[t0+128], B1 = g_b2[t0+128], C1 = g_c2[t0+128];
    float S0 = g_S[t0], S1 = g_S[t0+128];
    float lb0 = g_ld2[t0] + LOG4F, lb1 = g_ld2[t0+128] + LOG4F;

    unsigned long long both0 = 0ULL, both1 = 0ULL;
    bool c0 = false, c1 = false;
    #pragma unroll 4
    for (int g = 0; g < NG; g++) {
        float cx = s_cx[g], cy = s_cy[g], hw = s_hw[g], hh = s_hh[g];
        float dx0 = fabsf(xc0 - cx), dy0 = fabsf(yc0 - cy);
        float dx1 = fabsf(xc1 - cx), dy1 = fabsf(yc1 - cy);
        bool ib0 = (dx0 < hw) & (dy0 < hh);
        bool ic0 = (dx0 < rad) & (dy0 < rad);
        bool ib1 = (dx1 < hw) & (dy1 < hh);
        bool ic1 = (dx1 < rad) & (dy1 < rad);
        c0 |= ib0 | ic0; c1 |= ib1 | ic1;
        if (ib0 & ic0) both0 |= (1ULL << g);
        if (ib1 & ic1) both1 |= (1ULL << g);
    }
    float pc0 = c0 ? 0.f : 1e6f;
    float pc1 = c1 ? 0.f : 1e6f;
    size_t rowbase = (size_t)b * NG * NA + a0;

    for (int g = 0; g < NG; g++) {
        float2* dst = g_ic + rowbase + (size_t)g * NA;
        if (!s_val[g]) {
            dst[0]   = make_float2(0.f, 2e9f);
            dst[128] = make_float2(0.f, 2e9f);
            continue;
        }
        float ga = s_a1[g], gb = s_b1[g], gc = s_c1[g];
        float cx = s_cx[g], cy = s_cy[g];
        float lg1 = s_ld1[g];
        float lc0 = g_lc[s_cls[g] * BA + t0];
        float lc1 = g_lc[s_cls[g] * BA + t0 + 128];
        // anchor 0
        {
            float Af = ga + A0, Bf = gb + B0, Cf = gc + C0;
            float dx = cx - bx0, dy = cy - by0;
            float den = Af * Bf - Cf * Cf + 1e-8f;
            float rden = __fdividef(1.f, den);
            float t1 = 0.25f * (Af*dy*dy + Bf*dx*dx) * rden;
            float t2 = -0.5f * Cf * dx * dy * rden;
            float t3 = 0.5f * (__logf(den) - (lg1 + lb0));
            float bd = fminf(fmaxf(t1 + t2 + t3, 1e-8f), 100.f);
            float q = fminf(fmaxf(1.f - __expf(-bd), 1e-20f), 1.f);
            float iou = 1.f - q * __frsqrt_rn(q);
            float pb = ((both0 >> g) & 1ULL) ? 0.f : 1e5f;
            float cost = fmaf(-3.f, __logf(iou + 1e-8f), S0 + lc0 + pb + pc0);
            dst[0] = make_float2(iou, cost);
        }
        // anchor 1
        {
            float Af = ga + A1, Bf = gb + B1, Cf = gc + C1;
            float dx = cx - bx1, dy = cy - by1;
            float den = Af * Bf - Cf * Cf + 1e-8f;
            float rden = __fdividef(1.f, den);
            float t1 = 0.25f * (Af*dy*dy + Bf*dx*dx) * rden;
            float t2 = -0.5f * Cf * dx * dy * rden;
            float t3 = 0.5f * (__logf(den) - (lg1 + lb1));
            float bd = fminf(fmaxf(t1 + t2 + t3, 1e-8f), 100.f);
            float q = fminf(fmaxf(1.f - __expf(-bd), 1e-20f), 1.f);
            float iou = 1.f - q * __frsqrt_rn(q);
            float pb = ((both1 >> g) & 1ULL) ? 0.f : 1e5f;
            float cost = fmaf(-3.f, __logf(iou + 1e-8f), S1 + lc1 + pb + pc1);
            dst[128] = make_float2(iou, cost);
        }
    }
}

// ---------------- K3: per-(b,g) dyn_k + matching threshold ----------------
// Warp-distributed top-10 lists: lanes 0..9 hold the list (lane 9 = threshold).
__device__ __forceinline__ bool pless(float c1, int i1, float c2, int i2) {
    return (c1 < c2) || (c1 == c2 && i1 < i2);
}

// insert value c into descending max-list held in tv (lanes 0..9)
__device__ __forceinline__ void wins_top(float& tv, int lane, float c) {
    unsigned bm = __ballot_sync(FULLM, (lane < 10) && (c > tv)) & 0x3FFu;
    if (bm) {
        int p = __ffs(bm) - 1;
        float up = __shfl_up_sync(FULLM, tv, 1);
        if (lane < 10 && lane >= p) tv = (lane == p) ? c : up;
    }
}
// insert pair (c,i) into ascending min-list held in (bcv,biv) (lanes 0..9)
__device__ __forceinline__ void wins_bot(float& bcv, int& biv, int lane, float c, int i) {
    unsigned bm = __ballot_sync(FULLM, (lane < 10) && pless(c, i, bcv, biv)) & 0x3FFu;
    if (bm) {
        int p = __ffs(bm) - 1;
        float uc = __shfl_up_sync(FULLM, bcv, 1);
        int   ui = __shfl_up_sync(FULLM, biv, 1);
        if (lane < 10 && lane >= p) { bcv = (lane == p) ? c : uc; biv = (lane == p) ? i : ui; }
    }
}

__global__ void k_select() {
    int bg = blockIdx.x;
    int tid = threadIdx.x;
    int w = tid >> 5, lane = tid & 31;
    if (!g_gvalid[bg]) {
        if (tid == 0) { g_dynk[bg] = 0; g_thrC[bg] = -3.0e38f; g_thrI[bg] = -1; }
        return;
    }
    const float4* __restrict__ row4 = (const float4*)(g_ic + (size_t)bg * NA);

    float tv = -1.f;                       // top-iou list (desc), lanes 0..9
    float bcv = 3.0e38f; int biv = 0x7fffffff;  // bot-cost list (asc), lanes 0..9

    int base = w * 1344;                   // 1344 float4 per warp = 2688 anchors
    for (int s = 0; s < 42; s++) {
        int idx = base + s * 32 + lane;
        float4 v = row4[idx];
        int a0 = idx * 2, a1 = idx * 2 + 1;
        float e0 = (v.y < 1e6f) ? v.x : 0.f;    // cand <=> cost < 1e6 (penalty separation)
        float e1 = (v.w < 1e6f) ? v.z : 0.f;

        // top-iou: threshold check, then rare warp-collective inserts
        float thr = __shfl_sync(FULLM, tv, 9);
        unsigned m = __ballot_sync(FULLM, e0 > thr);
        while (m) {
            int src = __ffs(m) - 1; m &= m - 1;
            wins_top(tv, lane, __shfl_sync(FULLM, e0, src));
        }
        thr = __shfl_sync(FULLM, tv, 9);
        m = __ballot_sync(FULLM, e1 > thr);
        while (m) {
            int src = __ffs(m) - 1; m &= m - 1;
            wins_top(tv, lane, __shfl_sync(FULLM, e1, src));
        }

        // bot-cost
        float tc = __shfl_sync(FULLM, bcv, 9);
        int   ti = __shfl_sync(FULLM, biv, 9);
        m = __ballot_sync(FULLM, pless(v.y, a0, tc, ti));
        while (m) {
            int src = __ffs(m) - 1; m &= m - 1;
            float c = __shfl_sync(FULLM, v.y, src);
            int   i = __shfl_sync(FULLM, a0, src);
            wins_bot(bcv, biv, lane, c, i);
        }
        tc = __shfl_sync(FULLM, bcv, 9);
        ti = __shfl_sync(FULLM, biv, 9);
        m = __ballot_sync(FULLM, pless(v.w, a1, tc, ti));
        while (m) {
            int src = __ffs(m) - 1; m &= m - 1;
            float c = __shfl_sync(FULLM, v.w, src);
            int   i = __shfl_sync(FULLM, a1, src);
            wins_bot(bcv, biv, lane, c, i);
        }
    }

    __shared__ float s_t[8][10], s_c[8][10];
    __shared__ int   s_i[8][10];
    if (lane < 10) { s_t[w][lane] = tv; s_c[w][lane] = bcv; s_i[w][lane] = biv; }
    __syncthreads();

    if (w == 0) {
        for (int ww = 1; ww < 8; ww++) {
            #pragma unroll
            for (int j = 0; j < 10; j++) {
                wins_top(tv, lane, s_t[ww][j]);
                wins_bot(bcv, biv, lane, s_c[ww][j], s_i[ww][j]);
            }
        }
        float x = (lane < 10) ? tv : 0.f;
        #pragma unroll
        for (int o = 16; o > 0; o >>= 1) x += __shfl_xor_sync(FULLM, x, o);
        int k = (int)x;
        if (k < 1) k = 1;
        if (k > 10) k = 10;
        float thrC = __shfl_sync(FULLM, bcv, k - 1);   // k-th smallest pair
        int   thrI = __shfl_sync(FULLM, biv, k - 1);
        if (lane == 0) { g_dynk[bg] = k; g_thrC[bg] = thrC; g_thrI[bg] = thrI; }
    }
}

// ---------------- K5: match resolution + loss accumulation ----------------
__global__ void k_loss(const float* __restrict__ o8,
                       const float* __restrict__ o16,
                       const float* __restrict__ o32) {
    int b = blockIdx.x / 168;
    int t = blockIdx.x * 128 + threadIdx.x;
    int a = t - b * NA;
    __shared__ float s_thrC[NG], s_cx[NG], s_cy[NG], s_a1[NG], s_b1[NG], s_c1[NG], s_d1s[NG];
    __shared__ int   s_thrI[NG], s_k[NG], s_cls[NG];
    if (threadIdx.x < NG) {
        int gi = b * NG + threadIdx.x;
        s_thrC[threadIdx.x] = g_thrC[gi]; s_thrI[threadIdx.x] = g_thrI[gi]; s_k[threadIdx.x] = g_dynk[gi];
        s_cx[threadIdx.x] = g_gcx[gi]; s_cy[threadIdx.x] = g_gcy[gi];
        s_a1[threadIdx.x] = g_ga1[gi]; s_b1[threadIdx.x] = g_gb1[gi]; s_c1[threadIdx.x] = g_gc1[gi];
        s_d1s[threadIdx.x] = g_gd1s[gi]; s_cls[threadIdx.x] = g_gcls[gi];
    }
    __syncthreads();
    const float2* __restrict__ col = g_ic + (size_t)b * NG * NA + a;
    int cnt = 0, mg = 0, ming = 0;
    bool found = false;
    float minc = 3.4e38f, miniou = 0.f, pisum = 0.f;
    #pragma unroll 4
    for (int g = 0; g < NG; g++) {
        float2 ic = col[(size_t)g * NA];
        bool m = (s_k[g] > 0) && ((ic.y < s_thrC[g]) || (ic.y == s_thrC[g] && a <= s_thrI[g]));
        if (m) { cnt++; if (!found) { mg = g; found = true; } pisum += ic.x; }
        if (ic.y < minc) { minc = ic.y; ming = g; miniou = ic.x; }
    }
    bool fg = cnt > 0;
    float pi = pisum;
    if (cnt > 1) { mg = ming; pi = miniou; }   // conflict -> one-hot argmin
    float obj = g_obj[t];
    float fo = fg ? 1.f : 0.f;
    float lobj = fmaxf(obj, 0.f) - obj * fo + __logf(1.f + __expf(-fabsf(obj)));
    float liou = 0.f, lcls = 0.f;
    if (fg) {
        float bx = g_bx[t], by = g_by[t];
        float a2 = g_a2[t], b2 = g_b2[t], c2 = g_c2[t], d2s = g_d2s[t];
        float Af = a2 + s_a1[mg], Bf = b2 + s_b1[mg], Cf = c2 + s_c1[mg];
        float dx = bx - s_cx[mg], dy = by - s_cy[mg];
        float den = Af * Bf - Cf * Cf + 1e-8f;
        float rden = __fdividef(1.f, den);
        float t1 = 0.25f * (Af*dy*dy + Bf*dx*dx) * rden;
        float t2 = -0.5f * Cf * dx * dy * rden;
        float t3 = 0.5f * __logf(__fdividef(den, 4.f * s_d1s[mg] * d2s + 1e-8f));
        float bd = fminf(fmaxf(t1 + t2 + t3, 1e-8f), 100.f);
        float q = fminf(fmaxf(1.f - __expf(-bd), 1e-20f), 1.f);
        float ioum = 1.f - q * __frsqrt_rn(q);
        liou = 1.f - ioum;
        const float* src; int hw, i;
        if (a < L0N)      { src = o8;  hw = 16384; i = a; }
        else if (a < L1N) { src = o16; hw = 4096;  i = a - L0N; }
        else              { src = o32; hw = 1024;  i = a - L1N; }
        const float* pc = src + ((size_t)b * 21 + 6) * hw + i;
        int mcls = s_cls[mg];
        #pragma unroll
        for (int c = 0; c < NC; c++) {
            float x = pc[(size_t)c * hw];
            float tg = (c == mcls) ? pi : 0.f;
            lcls += fmaxf(x, 0.f) - x * tg + __logf(1.f + __expf(-fabsf(x)));
        }
    }
    #pragma unroll
    for (int o = 16; o > 0; o >>= 1) {
        liou += __shfl_down_sync(0xffffffffu, liou, o);
        lobj += __shfl_down_sync(0xffffffffu, lobj, o);
        lcls += __shfl_down_sync(0xffffffffu, lcls, o);
        fo   += __shfl_down_sync(0xffffffffu, fo, o);
    }
    __shared__ float rs[4][4];
    int w = threadIdx.x >> 5, lane = threadIdx.x & 31;
    if (lane == 0) { rs[0][w] = liou; rs[1][w] = lobj; rs[2][w] = lcls; rs[3][w] = fo; }
    __syncthreads();
    if (threadIdx.x == 0) {
        atomicAdd(&g_acc[0], rs[0][0] + rs[0][1] + rs[0][2] + rs[0][3]);
        atomicAdd(&g_acc[1], rs[1][0] + rs[1][1] + rs[1][2] + rs[1][3]);
        atomicAdd(&g_acc[2], rs[2][0] + rs[2][1] + rs[2][2] + rs[2][3]);
        atomicAdd(&g_acc[3], rs[3][0] + rs[3][1] + rs[3][2] + rs[3][3]);
    }
}

// ---------------- K6: finalize ----------------
__global__ void k_final(float* __restrict__ out, int n) {
    if (threadIdx.x == 0) {
        float nfg = g_acc[3];
        float nf = fmaxf(nfg, 1.f);
        float liou = g_acc[0] / nf;
        float lobj = g_acc[1] / nf;
        float lcls = g_acc[2] / nf;
        float li5 = 5.f * liou;
        float loss = li5 + lobj + lcls;
        if (n > 0) out[0] = loss;
        if (n > 1) out[1] = li5;
        if (n > 2) out[2] = lobj;
        if (n > 3) out[3] = lcls;
        if (n > 4) out[4] = 0.f;
        if (n > 5) out[5] = nfg / fmaxf(g_acc[4], 1.f);
        for (int i = 6; i < n; i++) out[i] = 0.f;
    }
}

// ---------------- launch ----------------
extern "C" void kernel_launch(void* const* d_in, const int* in_sizes, int n_in,
                              void* d_out, int out_size) {
    const float* o8     = (const float*)d_in[0];
    const float* o16    = (const float*)d_in[1];
    const float* o32    = (const float*)d_in[2];
    const float* labels = (const float*)d_in[3];
    float* out = (float*)d_out;

    k_gt<<<1, 512>>>(labels);
    k_decode<<<BA / 128, 128>>>(o8, o16, o32);
    k_cost<<<672, 128>>>();
    k_select<<<NBG, 256>>>();
    k_loss<<<BA / 128, 128>>>(o8, o16, o32);
    k_final<<<1, 32>>>(out, out_size);
}